// round 10
// baseline (speedup 1.0000x reference)
#include <cuda_runtime.h>
#include <stdint.h>
#include <float.h>

#define NROWS 8192
#define NCOLS 1000
#define NT 256
#define WPB 8                 // warps (rows) per block
#define NB (NROWS / WPB)      // 1024 blocks
#define NQ 26
// r[0..11]  : top2 pairs for 6 sources (max, second)
// r[12]     : sum e^{s}
// r[13]     : sum e^{s/T}
// r[14+j]   : S1_j = sum e^{x_j/T}
// r[20+j]   : S2_j = sum e^{x_j/T} * (s/T)

__device__ float g_ce[NROWS];
__device__ float g_a[NROWS];
__device__ float g_mx[NROWS];
__device__ int   g_ticket;    // zero-init; reset by last block each run

__device__ __forceinline__ void combine26(float* r, const float* t) {
#pragma unroll
    for (int j = 0; j < 6; j++) {
        float n0 = fmaxf(r[2 * j], t[2 * j]);
        float n1 = fmaxf(fminf(r[2 * j], t[2 * j]),
                         fmaxf(r[2 * j + 1], t[2 * j + 1]));
        r[2 * j] = n0;
        r[2 * j + 1] = n1;
    }
#pragma unroll
    for (int i = 12; i < NQ; i++) r[i] += t[i];
}

__global__ __launch_bounds__(NT, 3)
void fused_kernel(const float* __restrict__ t1, const float* __restrict__ t2,
                  const float* __restrict__ t3, const float* __restrict__ t4,
                  const float* __restrict__ t5, const float* __restrict__ os,
                  const int* __restrict__ tg, float* __restrict__ out) {
    const int tid  = threadIdx.x;
    const int lane = tid & 31;
    const int wid  = tid >> 5;
    const int row  = blockIdx.x * WPB + wid;
    const long base = (long)row * NCOLS;
    const int target = __ldg(tg + row);

    const float INV_T   = 0.05f;   // 1/T_KD
    const float T2      = 400.f;   // T_KD^2
    const float INV_TTH = 0.5f;    // 1/T_TH

    float r[NQ];
#pragma unroll
    for (int i = 0; i < 12; i++) r[i] = -FLT_MAX;
#pragma unroll
    for (int i = 12; i < NQ; i++) r[i] = 0.f;

    const float4* ps = (const float4*)(os + base);
    const float4* p0 = (const float4*)(t1 + base);
    const float4* p1 = (const float4*)(t2 + base);
    const float4* p2 = (const float4*)(t3 + base);
    const float4* p3 = (const float4*)(t4 + base);
    const float4* p4 = (const float4*)(t5 + base);

    // Staggered-consumption body: out_s is loaded first and consumed first;
    // teacher j's vector has ~j*25 issued instructions of slack before use.
#define TEACH(j, vv)                                                          \
    {                                                                         \
        float xk[4] = {vv.x, vv.y, vv.z, vv.w};                               \
        _Pragma("unroll")                                                     \
        for (int k = 0; k < 4; k++) {                                         \
            float xv = xk[k];                                                 \
            float e = __expf(xv * INV_T);                                     \
            r[14 + j] += e;                                                   \
            r[20 + j] = fmaf(e, lpw[k], r[20 + j]);                           \
            float nm0 = fmaxf(r[2 * j], xv);                                  \
            r[2 * j + 1] = fmaxf(r[2 * j + 1], fminf(r[2 * j], xv));          \
            r[2 * j] = nm0;                                                   \
            if (j == 0) msum[k] = xv; else msum[k] += xv;                     \
        }                                                                     \
    }

#define BODY(q)                                                               \
    {                                                                         \
        float4 vs = __ldg(ps + (q));                                          \
        float4 v0 = __ldg(p0 + (q));                                          \
        float4 v1 = __ldg(p1 + (q));                                          \
        float4 v2 = __ldg(p2 + (q));                                          \
        float4 v3 = __ldg(p3 + (q));                                          \
        float4 v4 = __ldg(p4 + (q));                                          \
        float lpw[4], msum[4];                                                \
        {   /* out_s block: consumes only vs */                               \
            float sk[4] = {vs.x, vs.y, vs.z, vs.w};                           \
            _Pragma("unroll")                                                 \
            for (int k = 0; k < 4; k++) {                                     \
                lpw[k] = sk[k] * INV_T;                                       \
                float u = __expf(lpw[k]);                                     \
                float u2 = u * u, u4 = u2 * u2, u5 = u4 * u;                  \
                float u10 = u5 * u5;                                          \
                r[12] += u10 * u10;   /* e^s = u^20 */                        \
                r[13] += u;                                                   \
            }                                                                 \
        }                                                                     \
        TEACH(0, v0)                                                          \
        TEACH(1, v1)                                                          \
        TEACH(2, v2)                                                          \
        TEACH(3, v3)                                                          \
        TEACH(4, v4)                                                          \
        {   /* mimic block */                                                 \
            _Pragma("unroll")                                                 \
            for (int k = 0; k < 4; k++) {                                     \
                float m = msum[k] * 0.2f;                                     \
                float e = __expf(m * INV_T);                                  \
                r[19] += e;                                                   \
                r[25] = fmaf(e, lpw[k], r[25]);                               \
                float nm0 = fmaxf(r[10], m);                                  \
                r[11] = fmaxf(r[11], fminf(r[10], m));                        \
                r[10] = nm0;                                                  \
            }                                                                 \
        }                                                                     \
    }

    // 7 full iterations: warp covers float4[0..223]
#pragma unroll 2
    for (int it = 0; it < 7; it++) {
        BODY(it * 32 + lane)
    }
    // tail: float4[224..249] (26 lanes)
    if (lane < 26) {
        BODY(224 + lane)
    }
#undef BODY
#undef TEACH

    // ---- Target logits (deferred; L2-hot; uniform address per warp) ----
    float tq[7];
    tq[0] = __ldg(t1 + base + target);
    tq[1] = __ldg(t2 + base + target);
    tq[2] = __ldg(t3 + base + target);
    tq[3] = __ldg(t4 + base + target);
    tq[4] = __ldg(t5 + base + target);
    tq[6] = __ldg(os + base + target);
    // Same association as the in-loop mimic running sum (sequential adds)
    tq[5] = ((((tq[0] + tq[1]) + tq[2]) + tq[3]) + tq[4]) * 0.2f;

    // ---- Single warp-level reduction of all 26 quantities ----
#pragma unroll
    for (int o = 16; o > 0; o >>= 1) {
        float t[NQ];
#pragma unroll
        for (int i = 0; i < NQ; i++) t[i] = __shfl_xor_sync(0xffffffffu, r[i], o);
        combine26(r, t);
    }

    if (lane == 0) {
        float CE   = __logf(r[12]) - tq[6];
        float lseT = __logf(r[13]);

        float tmax = r[0];
#pragma unroll
        for (int j = 1; j < 5; j++) tmax = fmaxf(tmax, r[2 * j]);

        float margins[6], kd[6];
#pragma unroll
        for (int j = 0; j < 6; j++) {
            kd[j]      = -T2 * (r[20 + j] / r[14 + j] - lseT);
            margins[j] = (tq[j] == r[2 * j]) ? (r[2 * j] - r[2 * j + 1]) : 0.f;
        }
        float mm = margins[0];
#pragma unroll
        for (int j = 1; j < 6; j++) mm = fmaxf(mm, margins[j]);
        float se = 0.f, A = 0.f;
#pragma unroll
        for (int j = 0; j < 6; j++) {
            float e = __expf((margins[j] - mm) * INV_TTH);
            se += e;
            A  += e * tq[j] * (kd[j] - CE);
        }
        g_ce[row] = CE;
        g_a[row]  = A / se;
        g_mx[row] = tmax;
        __threadfence();   // order this row's results before the ticket bump
    }

    // ---- last-block finalize ----
    __shared__ bool amLast;
    __shared__ float s1[WPB], s2[WPB], s3[WPB];
    __syncthreads();
    if (tid == 0) {
        int t = atomicAdd(&g_ticket, 1);
        amLast = (t == NB - 1);
    }
    __syncthreads();
    if (!amLast) return;
    __threadfence();

    const float4* c4 = (const float4*)g_ce;
    const float4* a4 = (const float4*)g_a;
    const float4* m4 = (const float4*)g_mx;

    float ce = 0.f, a = 0.f, mx = -FLT_MAX;
#pragma unroll
    for (int i = 0; i < 8; i++) {          // 2048 float4 per array / 256 threads
        int idx = tid + i * NT;
        float4 c = c4[idx], aa = a4[idx], m = m4[idx];
        ce += (c.x + c.y) + (c.z + c.w);
        a  += (aa.x + aa.y) + (aa.z + aa.w);
        mx  = fmaxf(mx, fmaxf(fmaxf(m.x, m.y), fmaxf(m.z, m.w)));
    }
#pragma unroll
    for (int o = 16; o > 0; o >>= 1) {
        ce += __shfl_xor_sync(0xffffffffu, ce, o);
        a  += __shfl_xor_sync(0xffffffffu, a, o);
        mx  = fmaxf(mx, __shfl_xor_sync(0xffffffffu, mx, o));
    }
    if (lane == 0) { s1[wid] = ce; s2[wid] = a; s3[wid] = mx; }
    __syncthreads();
    if (wid == 0) {
        ce = (lane < WPB) ? s1[lane] : 0.f;
        a  = (lane < WPB) ? s2[lane] : 0.f;
        mx = (lane < WPB) ? s3[lane] : -FLT_MAX;
#pragma unroll
        for (int o = 4; o > 0; o >>= 1) {
            ce += __shfl_xor_sync(0xffffffffu, ce, o);
            a  += __shfl_xor_sync(0xffffffffu, a, o);
            mx  = fmaxf(mx, __shfl_xor_sync(0xffffffffu, mx, o));
        }
        if (lane == 0) {
            const float invB = 1.0f / (float)NROWS;
            out[0] = ce * invB + (0.8f / mx) * (a * invB);
            g_ticket = 0;   // reset for next graph replay (deterministic)
        }
    }
}

extern "C" void kernel_launch(void* const* d_in, const int* in_sizes, int n_in,
                              void* d_out, int out_size) {
    const float* t1 = (const float*)d_in[0];
    const float* t2 = (const float*)d_in[1];
    const float* t3 = (const float*)d_in[2];
    const float* t4 = (const float*)d_in[3];
    const float* t5 = (const float*)d_in[4];
    const float* os = (const float*)d_in[5];
    const int*   tg = (const int*)d_in[6];

    fused_kernel<<<NB, NT>>>(t1, t2, t3, t4, t5, os, tg, (float*)d_out);
}

// round 11
// speedup vs baseline: 1.1996x; 1.1996x over previous
#include <cuda_runtime.h>
#include <stdint.h>
#include <float.h>

#define NROWS 8192
#define NCOLS 1000
#define NT 256
#define WPB 8                 // warps (rows) per block
#define NB (NROWS / WPB)      // 1024 blocks
#define NQ 26
// r[0..11]  : top2 pairs for 6 sources (max, second)
// r[12]     : sum e^{s}
// r[13]     : sum e^{s/T}
// r[14+j]   : S1_j = sum e^{x_j/T}
// r[20+j]   : S2_j = sum e^{x_j/T} * (s/T)

__device__ float g_ce[NROWS];
__device__ float g_a[NROWS];
__device__ float g_mx[NROWS];
__device__ int   g_ticket;    // zero-init; reset by last block each run

__device__ __forceinline__ void combine26(float* r, const float* t) {
#pragma unroll
    for (int j = 0; j < 6; j++) {
        float n0 = fmaxf(r[2 * j], t[2 * j]);
        float n1 = fmaxf(fminf(r[2 * j], t[2 * j]),
                         fmaxf(r[2 * j + 1], t[2 * j + 1]));
        r[2 * j] = n0;
        r[2 * j + 1] = n1;
    }
#pragma unroll
    for (int i = 12; i < NQ; i++) r[i] += t[i];
}

__global__ __launch_bounds__(NT, 4)
void fused_kernel(const float* __restrict__ t1, const float* __restrict__ t2,
                  const float* __restrict__ t3, const float* __restrict__ t4,
                  const float* __restrict__ t5, const float* __restrict__ os,
                  const int* __restrict__ tg, float* __restrict__ out) {
    const int tid  = threadIdx.x;
    const int lane = tid & 31;
    const int wid  = tid >> 5;
    const int row  = blockIdx.x * WPB + wid;
    const long base = (long)row * NCOLS;

    const float INV_T   = 0.05f;   // 1/T_KD
    const float T2      = 400.f;   // T_KD^2
    const float INV_TTH = 0.5f;    // 1/T_TH

    float r[NQ];
#pragma unroll
    for (int i = 0; i < 12; i++) r[i] = -FLT_MAX;
#pragma unroll
    for (int i = 12; i < NQ; i++) r[i] = 0.f;

    const float4* p0 = (const float4*)(t1 + base);
    const float4* p1 = (const float4*)(t2 + base);
    const float4* p2 = (const float4*)(t3 + base);
    const float4* p3 = (const float4*)(t4 + base);
    const float4* p4 = (const float4*)(t5 + base);
    const float4* ps = (const float4*)(os + base);

#define BODY(q)                                                               \
    {                                                                         \
        float4 v0 = __ldg(p0 + (q));                                          \
        float4 v1 = __ldg(p1 + (q));                                          \
        float4 v2 = __ldg(p2 + (q));                                          \
        float4 v3 = __ldg(p3 + (q));                                          \
        float4 v4 = __ldg(p4 + (q));                                          \
        float4 vs = __ldg(ps + (q));                                          \
        float a0[4] = {v0.x, v0.y, v0.z, v0.w};                               \
        float a1[4] = {v1.x, v1.y, v1.z, v1.w};                               \
        float a2[4] = {v2.x, v2.y, v2.z, v2.w};                               \
        float a3[4] = {v3.x, v3.y, v3.z, v3.w};                               \
        float a4[4] = {v4.x, v4.y, v4.z, v4.w};                               \
        float as[4] = {vs.x, vs.y, vs.z, vs.w};                               \
        _Pragma("unroll")                                                     \
        for (int k = 0; k < 4; k++) {                                         \
            float m = (a0[k] + a1[k] + a2[k] + a3[k] + a4[k]) * 0.2f;         \
            float lpw = as[k] * INV_T;                                        \
            float u = __expf(lpw);                                            \
            float u2 = u * u, u4 = u2 * u2, u5 = u4 * u;                      \
            float u10 = u5 * u5;                                              \
            r[12] += u10 * u10; /* e^s = u^20 */                              \
            r[13] += u;                                                       \
            float x[6] = {a0[k], a1[k], a2[k], a3[k], a4[k], m};              \
            _Pragma("unroll")                                                 \
            for (int j = 0; j < 6; j++) {                                     \
                float xv = x[j];                                              \
                float e = __expf(xv * INV_T);                                 \
                r[14 + j] += e;                                               \
                r[20 + j] = fmaf(e, lpw, r[20 + j]);                          \
                float nm0 = fmaxf(r[2 * j], xv);                              \
                r[2 * j + 1] = fmaxf(r[2 * j + 1], fminf(r[2 * j], xv));      \
                r[2 * j] = nm0;                                               \
            }                                                                 \
        }                                                                     \
    }

    // 7 full iterations: warp covers float4[0..223]
#pragma unroll 2
    for (int it = 0; it < 7; it++) {
        BODY(it * 32 + lane)
    }
    // tail: float4[224..249] (26 lanes)
    if (lane < 26) {
        BODY(224 + lane)
    }
#undef BODY

    // ---- Target logits (deferred: no extra live regs in the hot loop) ----
    const int target = __ldg(tg + row);
    float tq[7];
    tq[0] = __ldg(t1 + base + target);
    tq[1] = __ldg(t2 + base + target);
    tq[2] = __ldg(t3 + base + target);
    tq[3] = __ldg(t4 + base + target);
    tq[4] = __ldg(t5 + base + target);
    tq[6] = __ldg(os + base + target);
    tq[5] = (tq[0] + tq[1] + tq[2] + tq[3] + tq[4]) * 0.2f;  // same assoc as BODY

    // ---- Single warp-level reduction of all 26 quantities ----
#pragma unroll
    for (int o = 16; o > 0; o >>= 1) {
        float t[NQ];
#pragma unroll
        for (int i = 0; i < NQ; i++) t[i] = __shfl_xor_sync(0xffffffffu, r[i], o);
        combine26(r, t);
    }

    if (lane == 0) {
        float CE   = __logf(r[12]) - tq[6];
        float lseT = __logf(r[13]);

        float tmax = r[0];
#pragma unroll
        for (int j = 1; j < 5; j++) tmax = fmaxf(tmax, r[2 * j]);

        float margins[6], kd[6];
#pragma unroll
        for (int j = 0; j < 6; j++) {
            kd[j]      = -T2 * (r[20 + j] / r[14 + j] - lseT);
            margins[j] = (tq[j] == r[2 * j]) ? (r[2 * j] - r[2 * j + 1]) : 0.f;
        }
        float mm = margins[0];
#pragma unroll
        for (int j = 1; j < 6; j++) mm = fmaxf(mm, margins[j]);
        float se = 0.f, A = 0.f;
#pragma unroll
        for (int j = 0; j < 6; j++) {
            float e = __expf((margins[j] - mm) * INV_TTH);
            se += e;
            A  += e * tq[j] * (kd[j] - CE);
        }
        g_ce[row] = CE;
        g_a[row]  = A / se;
        g_mx[row] = tmax;
        __threadfence();   // order this row's results before the ticket bump
    }

    // ---- last-block finalize ----
    __shared__ bool amLast;
    __shared__ float s1[WPB], s2[WPB], s3[WPB];
    __syncthreads();
    if (tid == 0) {
        int t = atomicAdd(&g_ticket, 1);
        amLast = (t == NB - 1);
    }
    __syncthreads();
    if (!amLast) return;
    __threadfence();

    const float4* c4 = (const float4*)g_ce;
    const float4* a4 = (const float4*)g_a;
    const float4* m4 = (const float4*)g_mx;

    float ce = 0.f, a = 0.f, mx = -FLT_MAX;
#pragma unroll
    for (int i = 0; i < 8; i++) {          // 2048 float4 per array / 256 threads
        int idx = tid + i * NT;
        float4 c = c4[idx], aa = a4[idx], m = m4[idx];
        ce += (c.x + c.y) + (c.z + c.w);
        a  += (aa.x + aa.y) + (aa.z + aa.w);
        mx  = fmaxf(mx, fmaxf(fmaxf(m.x, m.y), fmaxf(m.z, m.w)));
    }
#pragma unroll
    for (int o = 16; o > 0; o >>= 1) {
        ce += __shfl_xor_sync(0xffffffffu, ce, o);
        a  += __shfl_xor_sync(0xffffffffu, a, o);
        mx  = fmaxf(mx, __shfl_xor_sync(0xffffffffu, mx, o));
    }
    if (lane == 0) { s1[wid] = ce; s2[wid] = a; s3[wid] = mx; }
    __syncthreads();
    if (wid == 0) {
        ce = (lane < WPB) ? s1[lane] : 0.f;
        a  = (lane < WPB) ? s2[lane] : 0.f;
        mx = (lane < WPB) ? s3[lane] : -FLT_MAX;
#pragma unroll
        for (int o = 4; o > 0; o >>= 1) {
            ce += __shfl_xor_sync(0xffffffffu, ce, o);
            a  += __shfl_xor_sync(0xffffffffu, a, o);
            mx  = fmaxf(mx, __shfl_xor_sync(0xffffffffu, mx, o));
        }
        if (lane == 0) {
            const float invB = 1.0f / (float)NROWS;
            out[0] = ce * invB + (0.8f / mx) * (a * invB);
            g_ticket = 0;   // reset for next graph replay (deterministic)
        }
    }
}

extern "C" void kernel_launch(void* const* d_in, const int* in_sizes, int n_in,
                              void* d_out, int out_size) {
    const float* t1 = (const float*)d_in[0];
    const float* t2 = (const float*)d_in[1];
    const float* t3 = (const float*)d_in[2];
    const float* t4 = (const float*)d_in[3];
    const float* t5 = (const float*)d_in[4];
    const float* os = (const float*)d_in[5];
    const int*   tg = (const int*)d_in[6];

    fused_kernel<<<NB, NT>>>(t1, t2, t3, t4, t5, os, tg, (float*)d_out);
}